// round 2
// baseline (speedup 1.0000x reference)
#include <cuda_runtime.h>
#include <cstdint>

#define N_C 50000
#define N_V 100000
#define N_A 5000
#define E_C2V 1600000
#define E_A2V 1000000

// ---------------- static device scratch (no allocation) ----------------
__device__ __align__(16) float g_P_gv_v[N_V*32];
__device__ __align__(16) float g_P_hv_v[N_V*32];
__device__ __align__(16) float g_P_fv_v[N_V*32];
__device__ __align__(16) float g_P_ga_v[N_V*32];   // f_v_relu @ g_a_W1[14:46]
__device__ __align__(16) float g_P_gv_c[N_C*32];
__device__ __align__(16) float g_P_hv_a[N_A*32];
__device__ __align__(16) float g_P_ga_a[N_A*32];
__device__ __align__(16) float g_P_fa_a[N_A*32];
__device__ __align__(16) float g_acc_gv[N_V*32];
__device__ __align__(16) float g_acc_hv[N_V*32];
__device__ __align__(16) float g_acc_ga[N_A*32];
__device__ float g_cnt_gv[N_V];
__device__ float g_cnt_hv[N_V];
__device__ float g_cnt_ga[N_A];

static __device__ __forceinline__ void red2(float* p, float v0, float v1){
  asm volatile("red.global.add.v2.f32 [%0], {%1,%2};" :: "l"(p), "f"(v0), "f"(v1) : "memory");
}

// ---------------- zero accumulators ----------------
__global__ void k_zero(){
  int i = blockIdx.x*blockDim.x + threadIdx.x;
  int stride = gridDim.x*blockDim.x;
  for (int j=i;j<N_V*32;j+=stride){ g_acc_gv[j]=0.f; g_acc_hv[j]=0.f; }
  for (int j=i;j<N_V;j+=stride){ g_cnt_gv[j]=0.f; g_cnt_hv[j]=0.f; }
  for (int j=i;j<N_A*32;j+=stride) g_acc_ga[j]=0.f;
  for (int j=i;j<N_A;j+=stride) g_cnt_ga[j]=0.f;
}

// ---------------- per-node projections: out[n] = x[n] @ Wrows (din x 32) ----------------
static __device__ float* pre_out(int which){
  switch(which){
    case 0: return g_P_gv_v;
    case 1: return g_P_hv_v;
    case 2: return g_P_fv_v;
    case 3: return g_P_gv_c;
    case 4: return g_P_hv_a;
    case 5: return g_P_ga_a;
    default: return g_P_fa_a;
  }
}

__global__ void __launch_bounds__(256) k_pre(
    const float* __restrict__ x, int n_nodes, int din,
    const float* __restrict__ Wrows, int which)
{
  __shared__ float s_w[14*32];
  for (int i=threadIdx.x;i<din*32;i+=256) s_w[i]=Wrows[i];
  __syncthreads();
  int node = blockIdx.x*256 + threadIdx.x;
  if (node >= n_nodes) return;
  float* out = pre_out(which);
  float xr[14];
  const float* xp = x + (size_t)node*din;
  for (int k=0;k<din;k++) xr[k]=xp[k];
  float* op = out + (size_t)node*32;
#pragma unroll
  for (int cg=0;cg<8;cg++){
    float4 a = make_float4(0.f,0.f,0.f,0.f);
    for (int k=0;k<din;k++){
      float4 w = *(const float4*)&s_w[k*32+cg*4];
      a.x += xr[k]*w.x; a.y += xr[k]*w.y; a.z += xr[k]*w.z; a.w += xr[k]*w.w;
    }
    *(float4*)&op[cg*4] = a;
  }
}

// ---------------- fused per-edge MLP + scatter-add ----------------
// mode 0: c2v / g_v  : Ps=P_gv_c[s], Pt=P_gv_v[t], agg index = t -> acc_gv
// mode 1: a2v / h_v  : Ps=P_hv_a[s], Pt=P_hv_v[t], agg index = t -> acc_hv
// mode 2: a2v / g_a  : Ps=P_ga_a[s], Pt=P_ga_v[t], agg index = s -> acc_ga
__global__ void __launch_bounds__(256) k_edge(
    int nedges, int mode,
    const int* __restrict__ src, const int* __restrict__ tgt,
    const float* __restrict__ attr,
    const float* __restrict__ W1,  // full W1; we = row (rowoff_we)
    int rowoff_we,
    const float* __restrict__ b1,
    const float* __restrict__ W2, const float* __restrict__ b2)
{
  const float* Ps; const float* Pt; float* acc; float* cnt;
  if (mode == 0){ Ps=g_P_gv_c; Pt=g_P_gv_v; acc=g_acc_gv; cnt=g_cnt_gv; }
  else if (mode == 1){ Ps=g_P_hv_a; Pt=g_P_hv_v; acc=g_acc_hv; cnt=g_cnt_hv; }
  else { Ps=g_P_ga_a; Pt=g_P_ga_v; acc=g_acc_ga; cnt=g_cnt_ga; }

  __shared__ float s_W2[32*32];
  __shared__ float s_we[32], s_b1[32], s_b2[32];
  for (int i=threadIdx.x;i<32*32;i+=256) s_W2[i]=W2[i];
  if (threadIdx.x < 32){
    s_we[threadIdx.x] = W1[rowoff_we*32 + threadIdx.x];
    s_b1[threadIdx.x] = b1[threadIdx.x];
    s_b2[threadIdx.x] = b2[threadIdx.x];
  }
  __syncthreads();

  int e = blockIdx.x*256 + threadIdx.x;
  if (e >= nedges) return;
  int s = src[e], t = tgt[e];
  float at = attr[e];
  const float* ps = Ps + (size_t)s*32;
  const float* pt = Pt + (size_t)t*32;
  float h[32];
#pragma unroll
  for (int cg=0;cg<8;cg++){
    float4 a = *(const float4*)&ps[cg*4];
    float4 b = *(const float4*)&pt[cg*4];
    h[cg*4+0] = fmaxf(a.x + b.x + at*s_we[cg*4+0] + s_b1[cg*4+0], 0.f);
    h[cg*4+1] = fmaxf(a.y + b.y + at*s_we[cg*4+1] + s_b1[cg*4+1], 0.f);
    h[cg*4+2] = fmaxf(a.z + b.z + at*s_we[cg*4+2] + s_b1[cg*4+2], 0.f);
    h[cg*4+3] = fmaxf(a.w + b.w + at*s_we[cg*4+3] + s_b1[cg*4+3], 0.f);
  }
  int idx = (mode == 2) ? s : t;
  float* ac = acc + (size_t)idx*32;
#pragma unroll
  for (int jg=0;jg<8;jg++){
    float4 a = *(const float4*)&s_b2[jg*4];
#pragma unroll
    for (int k=0;k<32;k++){
      float4 w = *(const float4*)&s_W2[k*32+jg*4];
      a.x += h[k]*w.x; a.y += h[k]*w.y; a.z += h[k]*w.z; a.w += h[k]*w.w;
    }
    a.x = fmaxf(a.x,0.f); a.y = fmaxf(a.y,0.f);
    a.z = fmaxf(a.z,0.f); a.w = fmaxf(a.w,0.f);
    red2(ac + jg*4,     a.x, a.y);
    red2(ac + jg*4 + 2, a.z, a.w);
  }
  atomicAdd(cnt + idx, 1.0f);
}

// ---------------- f_v node MLP (77->32->32, relu out) fused with g_a projection ----------------
__global__ void __launch_bounds__(256) k_fv(
    const float* __restrict__ fvW1, const float* __restrict__ fvb1,
    const float* __restrict__ fvW2, const float* __restrict__ fvb2,
    const float* __restrict__ gaW1)
{
  __shared__ float s_W1[64*32];   // f_v W1 rows 13..76 (g part then h part)
  __shared__ float s_W2[32*32];
  __shared__ float s_Wg[32*32];   // g_a W1 rows 14..45
  __shared__ float s_b1[32], s_b2[32];
  for (int i=threadIdx.x;i<64*32;i+=256) s_W1[i]=fvW1[13*32+i];
  for (int i=threadIdx.x;i<32*32;i+=256){ s_W2[i]=fvW2[i]; s_Wg[i]=gaW1[14*32+i]; }
  if (threadIdx.x<32){ s_b1[threadIdx.x]=fvb1[threadIdx.x]; s_b2[threadIdx.x]=fvb2[threadIdx.x]; }
  __syncthreads();
  int n = blockIdx.x*256 + threadIdx.x;
  if (n >= N_V) return;
  float ig = 1.f/fmaxf(g_cnt_gv[n],1.f);
  float ih = 1.f/fmaxf(g_cnt_hv[n],1.f);
  float h[32];
#pragma unroll
  for (int c=0;c<32;c++) h[c] = g_P_fv_v[(size_t)n*32+c] + s_b1[c];
#pragma unroll 4
  for (int k=0;k<32;k++){
    float g = g_acc_gv[(size_t)n*32+k]*ig;
#pragma unroll
    for (int cg=0;cg<8;cg++){
      float4 w = *(const float4*)&s_W1[k*32+cg*4];
      h[cg*4+0]+=g*w.x; h[cg*4+1]+=g*w.y; h[cg*4+2]+=g*w.z; h[cg*4+3]+=g*w.w;
    }
  }
#pragma unroll 4
  for (int k=0;k<32;k++){
    float g = g_acc_hv[(size_t)n*32+k]*ih;
#pragma unroll
    for (int cg=0;cg<8;cg++){
      float4 w = *(const float4*)&s_W1[(32+k)*32+cg*4];
      h[cg*4+0]+=g*w.x; h[cg*4+1]+=g*w.y; h[cg*4+2]+=g*w.z; h[cg*4+3]+=g*w.w;
    }
  }
#pragma unroll
  for (int c=0;c<32;c++) h[c]=fmaxf(h[c],0.f);
  // layer 2 -> v = relu(h @ W2 + b2)   (relu_out=True; extra relu is idempotent)
  float v[32];
#pragma unroll
  for (int c=0;c<32;c++) v[c]=s_b2[c];
#pragma unroll 4
  for (int k=0;k<32;k++){
    float g = h[k];
#pragma unroll
    for (int cg=0;cg<8;cg++){
      float4 w = *(const float4*)&s_W2[k*32+cg*4];
      v[cg*4+0]+=g*w.x; v[cg*4+1]+=g*w.y; v[cg*4+2]+=g*w.z; v[cg*4+3]+=g*w.w;
    }
  }
#pragma unroll
  for (int c=0;c<32;c++) v[c]=fmaxf(v[c],0.f);
  // project to g_a layer-1 space: P_ga_v[n] = v @ gaW1[14:46]
  float o[32];
#pragma unroll
  for (int c=0;c<32;c++) o[c]=0.f;
#pragma unroll 4
  for (int k=0;k<32;k++){
    float g = v[k];
#pragma unroll
    for (int cg=0;cg<8;cg++){
      float4 w = *(const float4*)&s_Wg[k*32+cg*4];
      o[cg*4+0]+=g*w.x; o[cg*4+1]+=g*w.y; o[cg*4+2]+=g*w.z; o[cg*4+3]+=g*w.w;
    }
  }
#pragma unroll
  for (int cg=0;cg<8;cg++)
    *(float4*)&g_P_ga_v[(size_t)n*32+cg*4] = make_float4(o[cg*4],o[cg*4+1],o[cg*4+2],o[cg*4+3]);
}

// ---------------- f_a node MLP (46->32->32, relu out) -> d_out ----------------
__global__ void __launch_bounds__(256) k_fa(
    const float* __restrict__ faW1, const float* __restrict__ fab1,
    const float* __restrict__ faW2, const float* __restrict__ fab2,
    float* __restrict__ out)
{
  __shared__ float s_W1[32*32];   // f_a W1 rows 14..45
  __shared__ float s_W2[32*32];
  __shared__ float s_b1[32], s_b2[32];
  for (int i=threadIdx.x;i<32*32;i+=256){ s_W1[i]=faW1[14*32+i]; s_W2[i]=faW2[i]; }
  if (threadIdx.x<32){ s_b1[threadIdx.x]=fab1[threadIdx.x]; s_b2[threadIdx.x]=fab2[threadIdx.x]; }
  __syncthreads();
  int n = blockIdx.x*256 + threadIdx.x;
  if (n >= N_A) return;
  float ig = 1.f/fmaxf(g_cnt_ga[n],1.f);
  float h[32];
#pragma unroll
  for (int c=0;c<32;c++) h[c] = g_P_fa_a[(size_t)n*32+c] + s_b1[c];
#pragma unroll 4
  for (int k=0;k<32;k++){
    float g = g_acc_ga[(size_t)n*32+k]*ig;
#pragma unroll
    for (int cg=0;cg<8;cg++){
      float4 w = *(const float4*)&s_W1[k*32+cg*4];
      h[cg*4+0]+=g*w.x; h[cg*4+1]+=g*w.y; h[cg*4+2]+=g*w.z; h[cg*4+3]+=g*w.w;
    }
  }
#pragma unroll
  for (int c=0;c<32;c++) h[c]=fmaxf(h[c],0.f);
  float v[32];
#pragma unroll
  for (int c=0;c<32;c++) v[c]=s_b2[c];
#pragma unroll 4
  for (int k=0;k<32;k++){
    float g = h[k];
#pragma unroll
    for (int cg=0;cg<8;cg++){
      float4 w = *(const float4*)&s_W2[k*32+cg*4];
      v[cg*4+0]+=g*w.x; v[cg*4+1]+=g*w.y; v[cg*4+2]+=g*w.z; v[cg*4+3]+=g*w.w;
    }
  }
#pragma unroll
  for (int cg=0;cg<8;cg++)
    *(float4*)&out[(size_t)n*32+cg*4] = make_float4(
        fmaxf(v[cg*4+0],0.f), fmaxf(v[cg*4+1],0.f),
        fmaxf(v[cg*4+2],0.f), fmaxf(v[cg*4+3],0.f));
}

// ---------------- launch ----------------
extern "C" void kernel_launch(void* const* d_in, const int* in_sizes, int n_in,
                              void* d_out, int out_size)
{
  const float* x_c   = (const float*)d_in[0];
  const float* x_v   = (const float*)d_in[1];
  const float* x_a   = (const float*)d_in[2];
  const int*   c2v_s = (const int*)d_in[3];
  const int*   c2v_t = (const int*)d_in[4];
  const int*   a2v_s = (const int*)d_in[5];
  const int*   a2v_t = (const int*)d_in[6];
  const float* ea_c2v = (const float*)d_in[7];
  const float* ea_a2v = (const float*)d_in[8];
  const float* gvW1 = (const float*)d_in[9];
  const float* gvb1 = (const float*)d_in[10];
  const float* gvW2 = (const float*)d_in[11];
  const float* gvb2 = (const float*)d_in[12];
  const float* hvW1 = (const float*)d_in[13];
  const float* hvb1 = (const float*)d_in[14];
  const float* hvW2 = (const float*)d_in[15];
  const float* hvb2 = (const float*)d_in[16];
  const float* fvW1 = (const float*)d_in[17];
  const float* fvb1 = (const float*)d_in[18];
  const float* fvW2 = (const float*)d_in[19];
  const float* fvb2 = (const float*)d_in[20];
  const float* gaW1 = (const float*)d_in[21];
  const float* gab1 = (const float*)d_in[22];
  const float* gaW2 = (const float*)d_in[23];
  const float* gab2 = (const float*)d_in[24];
  const float* faW1 = (const float*)d_in[25];
  const float* fab1 = (const float*)d_in[26];
  const float* faW2 = (const float*)d_in[27];
  const float* fab2 = (const float*)d_in[28];
  float* out = (float*)d_out;

  k_zero<<<1024, 256>>>();

  // projections: out-slot, x, n, din, W-rows
  k_pre<<<(N_V+255)/256, 256>>>(x_v, N_V, 13, gvW1 + 0*32, 0);      // P_gv_v
  k_pre<<<(N_V+255)/256, 256>>>(x_v, N_V, 13, hvW1 + 0*32, 1);      // P_hv_v
  k_pre<<<(N_V+255)/256, 256>>>(x_v, N_V, 13, fvW1 + 0*32, 2);      // P_fv_v
  k_pre<<<(N_C+255)/256, 256>>>(x_c, N_C, 14, gvW1 + 13*32, 3);     // P_gv_c
  k_pre<<<(N_A+255)/256, 256>>>(x_a, N_A, 14, hvW1 + 13*32, 4);     // P_hv_a
  k_pre<<<(N_A+255)/256, 256>>>(x_a, N_A, 14, gaW1 + 0*32, 5);      // P_ga_a
  k_pre<<<(N_A+255)/256, 256>>>(x_a, N_A, 14, faW1 + 0*32, 6);      // P_fa_a

  // edge passes (left-to-right)
  k_edge<<<(E_C2V+255)/256, 256>>>(E_C2V, 0, c2v_s, c2v_t, ea_c2v,
                                   gvW1, 27, gvb1, gvW2, gvb2);
  k_edge<<<(E_A2V+255)/256, 256>>>(E_A2V, 1, a2v_s, a2v_t, ea_a2v,
                                   hvW1, 27, hvb1, hvW2, hvb2);

  // variable-node update fused with g_a layer-1 projection
  k_fv<<<(N_V+255)/256, 256>>>(fvW1, fvb1, fvW2, fvb2, gaW1);

  // right-to-left edge pass
  k_edge<<<(E_A2V+255)/256, 256>>>(E_A2V, 2, a2v_s, a2v_t, ea_a2v,
                                   gaW1, 46, gab1, gaW2, gab2);

  // cut-node update -> output
  k_fa<<<(N_A+255)/256, 256>>>(faW1, fab1, faW2, fab2, out);
}